// round 15
// baseline (speedup 1.0000x reference)
#include <cuda_runtime.h>
#include <stdint.h>

#define TOKENS 16384
#define DIM    4096
#define NE     64
#define BM     64
#define NTHR   256
#define NITER  32            // k chunks of 128
#define TAU    8e-3f
#define MAXF   32

// W fragments, fp16, k-permuted, paired layout:
// g_wfrag2[j][nb4][lane] = uint4{ b0(nb4), b1(nb4), b0(nb4+4), b1(nb4+4) }
// where for kstep j, lane (t=lane&3, r=lane>>2): n = nb*8 + r, k = j*16 + t*4,
// b0 = pack(W[n][k],W[n][k+1]) (kappa 2t,2t+1), b1 = pack(W[n][k+2],W[n][k+3]).
__device__ __align__(16) uint4 g_wfrag2[256 * 4 * 32];

// ---- smem: 3-stage x-only ring, 32KB per stage (64 rows x 128 fp32, 512B rows) ----
#define XSTAGE 32768
#define SMEM_TOTAL (3 * XSTAGE)      // 98304
// ---- epilogue aliases (post-mainloop only) ----
#define SLOG_OFF   32768             // 64 x 65 fp32
#define S1_OFF     49408
#define S2_OFF     49664
#define I1_OFF     49920
#define I2_OFF     50176
#define FENT_OFF   50432
#define NFLAG_OFF  50688
#define FTOK_OFF   50692
#define FCAND_OFF  50820
#define FVAL_OFF   51332

__device__ __forceinline__ uint32_t smem_u32(const void* p) {
    uint32_t a;
    asm("{ .reg .u64 t; cvta.to.shared.u64 t, %1; cvt.u32.u64 %0, t; }"
        : "=r"(a) : "l"(p));
    return a;
}

__device__ __forceinline__ uint32_t pack_f16x2(float f0, float f1) {
    uint32_t r;
    asm("cvt.rn.f16x2.f32 %0, %1, %2;" : "=r"(r) : "f"(f1), "f"(f0));  // f0 -> low
    return r;
}

__device__ __forceinline__ void mma16816(float c[4], const uint32_t a[4],
                                         uint32_t b0, uint32_t b1) {
    asm volatile(
        "mma.sync.aligned.m16n8k16.row.col.f32.f16.f16.f32 "
        "{%0,%1,%2,%3}, {%4,%5,%6,%7}, {%8,%9}, {%0,%1,%2,%3};"
        : "+f"(c[0]), "+f"(c[1]), "+f"(c[2]), "+f"(c[3])
        : "r"(a[0]), "r"(a[1]), "r"(a[2]), "r"(a[3]), "r"(b0), "r"(b1));
}

// ---------------- prep: W fp32 -> paired fp16 fragments ----------------
__global__ void prep_w(const float* __restrict__ W) {
    int idx = blockIdx.x * 256 + threadIdx.x;      // 0..32767
    int j    = idx >> 7;                           // kstep 0..255
    int nb4  = (idx >> 5) & 3;                     // n-block 0..3
    int lane = idx & 31;
    int n1 = nb4 * 8 + (lane >> 2);                // experts 0..31
    int n2 = n1 + 32;                              // experts 32..63
    int k  = j * 16 + (lane & 3) * 4;
    float4 va = *reinterpret_cast<const float4*>(W + (size_t)n1 * DIM + k);
    float4 vb = *reinterpret_cast<const float4*>(W + (size_t)n2 * DIM + k);
    g_wfrag2[idx] = make_uint4(pack_f16x2(va.x, va.y), pack_f16x2(va.z, va.w),
                               pack_f16x2(vb.x, vb.y), pack_f16x2(vb.z, vb.w));
}

// ---------------- main fused kernel: fp16 1-term, x-ring + B-from-L2 ----------------
__global__ __launch_bounds__(NTHR, 2)
void topk_gate_pipe5(const float* __restrict__ x, const float* __restrict__ Wf,
                     float* __restrict__ out_logits, float* __restrict__ out_scores,
                     float* __restrict__ out_loss)
{
    extern __shared__ char smem[];
    const uint32_t sb = smem_u32(smem);

    float* red   = reinterpret_cast<float*>(smem);
    float* slog  = reinterpret_cast<float*>(smem + SLOG_OFF);
    float* s_s1  = reinterpret_cast<float*>(smem + S1_OFF);
    float* s_s2  = reinterpret_cast<float*>(smem + S2_OFF);
    int*   s_i1  = reinterpret_cast<int*>(smem + I1_OFF);
    int*   s_i2  = reinterpret_cast<int*>(smem + I2_OFF);
    int*   s_fent= reinterpret_cast<int*>(smem + FENT_OFF);
    int*   s_nfl = reinterpret_cast<int*>(smem + NFLAG_OFF);
    int*   f_tok = reinterpret_cast<int*>(smem + FTOK_OFF);
    int*   f_cand= reinterpret_cast<int*>(smem + FCAND_OFF);
    float* f_val = reinterpret_cast<float*>(smem + FVAL_OFF);

    const int tid  = threadIdx.x;
    const int lane = tid & 31;
    const int wid  = tid >> 5;
    const int mh   = wid >> 2;          // m-half 0..1
    const int ks   = wid & 3;           // k-slice 0..3
    const size_t m_base = (size_t)blockIdx.x * BM;

    // ---- copy mapping: 8 x 16B chunks/thread; rows p*8 + (tid>>5), chunk tid&31 ----
    const int crow   = tid >> 5;                    // 0..7
    const int cchunk = tid & 31;                    // 0..31
    const int csw    = (cchunk ^ ((crow & 1) << 2)) * 16;   // parity swizzle
    const float* xg  = x + m_base * DIM;

#define COPY_STAGE(S, ST)                                                      \
    do {                                                                       \
        const uint32_t _xb = sb + (ST) * XSTAGE;                               \
        const float* _xs = xg + (S) * 128;                                     \
        _Pragma("unroll")                                                      \
        for (int p = 0; p < 8; p++) {                                          \
            int r = p * 8 + crow;                                              \
            uint32_t d = _xb + r * 512 + csw;                                  \
            const float* g = _xs + (size_t)r * DIM + cchunk * 4;               \
            asm volatile("cp.async.cg.shared.global [%0], [%1], 16;"           \
                         :: "r"(d), "l"(g));                                   \
        }                                                                      \
        asm volatile("cp.async.commit_group;");                                \
    } while (0)

    // consumer loop-invariant pieces
    const int r0row = mh * 32 + (lane >> 2);
    const int rpar  = ((lane >> 2) & 1) << 2;
    // chunk for kstep j_local: j_local*4 + (lane&3), physical = ^rpar
    const int cA  = (ks * 4 + (lane & 3)) ^ rpar;          // j_local = ks
    const int cB  = ((ks + 4) * 4 + (lane & 3)) ^ rpar;    // j_local = ks+4
    const int aoffA = r0row * 512 + cA * 16;
    const int aoffB = r0row * 512 + cB * 16;

    float acc[2][4][4], acc2[2][4][4];
    #pragma unroll
    for (int mg = 0; mg < 2; mg++)
        #pragma unroll
        for (int nt = 0; nt < 4; nt++)
            #pragma unroll
            for (int q = 0; q < 4; q++) { acc[mg][nt][q] = 0.f; acc2[mg][nt][q] = 0.f; }

    // prologue: stages 0,1 in flight
    COPY_STAGE(0, 0);
    COPY_STAGE(1, 1);

    #pragma unroll 1
    for (int s = 0; s < NITER; ++s) {
        asm volatile("cp.async.wait_group 1;" ::: "memory");
        __syncthreads();

        // refill stage s+2 into slot (s+2)%3 (held stage s-1, reads done pre-barrier)
        if (s + 2 < NITER) COPY_STAGE(s + 2, (s + 2) % 3);
        else asm volatile("cp.async.commit_group;");

        const char* xb = smem + (s % 3) * XSTAGE;

        // ================= kstep a: global J = 8s + ks =================
        {
            const uint4* wb = g_wfrag2 + (size_t)(8 * s + ks) * 128 + lane;
            const uint4 B0 = wb[0], B1 = wb[32], B2 = wb[64], B3 = wb[96];

            const float4 v0 = *reinterpret_cast<const float4*>(xb + aoffA);
            const float4 v1 = *reinterpret_cast<const float4*>(xb + aoffA + 8 * 512);
            const float4 v2 = *reinterpret_cast<const float4*>(xb + aoffA + 16 * 512);
            const float4 v3 = *reinterpret_cast<const float4*>(xb + aoffA + 24 * 512);

            uint32_t a0[4], a1[4];
            a0[0] = pack_f16x2(v0.x, v0.y);
            a0[1] = pack_f16x2(v1.x, v1.y);
            a0[2] = pack_f16x2(v0.z, v0.w);
            a0[3] = pack_f16x2(v1.z, v1.w);
            a1[0] = pack_f16x2(v2.x, v2.y);
            a1[1] = pack_f16x2(v3.x, v3.y);
            a1[2] = pack_f16x2(v2.z, v2.w);
            a1[3] = pack_f16x2(v3.z, v3.w);

            mma16816(acc[0][0],  a0, B0.x, B0.y);
            mma16816(acc[0][1],  a0, B1.x, B1.y);
            mma16816(acc[0][2],  a0, B2.x, B2.y);
            mma16816(acc[0][3],  a0, B3.x, B3.y);
            mma16816(acc[1][0],  a1, B0.x, B0.y);
            mma16816(acc[1][1],  a1, B1.x, B1.y);
            mma16816(acc[1][2],  a1, B2.x, B2.y);
            mma16816(acc[1][3],  a1, B3.x, B3.y);
            mma16816(acc2[0][0], a0, B0.z, B0.w);
            mma16816(acc2[0][1], a0, B1.z, B1.w);
            mma16816(acc2[0][2], a0, B2.z, B2.w);
            mma16816(acc2[0][3], a0, B3.z, B3.w);
            mma16816(acc2[1][0], a1, B0.z, B0.w);
            mma16816(acc2[1][1], a1, B1.z, B1.w);
            mma16816(acc2[1][2], a1, B2.z, B2.w);
            mma16816(acc2[1][3], a1, B3.z, B3.w);
        }

        // ================= kstep b: global J = 8s + ks + 4 =================
        {
            const uint4* wb = g_wfrag2 + (size_t)(8 * s + ks + 4) * 128 + lane;
            const uint4 B0 = wb[0], B1 = wb[32], B2 = wb[64], B3 = wb[96];

            const float4 v0 = *reinterpret_cast<const float4*>(xb + aoffB);
            const float4 v1 = *reinterpret_cast<const float4*>(xb + aoffB + 8 * 512);
            const float4 v2 = *reinterpret_cast<const float4*>(xb + aoffB + 16 * 512);
            const float4 v3 = *reinterpret_cast<const float4*>(xb + aoffB + 24 * 512);

            uint32_t a0[4], a1[4];
            a0[0] = pack_f16x2(v0.x, v0.y);
            a0[1] = pack_f16x2(v1.x, v1.y);
            a0[2] = pack_f16x2(v0.z, v0.w);
            a0[3] = pack_f16x2(v1.z, v1.w);
            a1[0] = pack_f16x2(v2.x, v2.y);
            a1[1] = pack_f16x2(v3.x, v3.y);
            a1[2] = pack_f16x2(v2.z, v2.w);
            a1[3] = pack_f16x2(v3.z, v3.w);

            mma16816(acc[0][0],  a0, B0.x, B0.y);
            mma16816(acc[0][1],  a0, B1.x, B1.y);
            mma16816(acc[0][2],  a0, B2.x, B2.y);
            mma16816(acc[0][3],  a0, B3.x, B3.y);
            mma16816(acc[1][0],  a1, B0.x, B0.y);
            mma16816(acc[1][1],  a1, B1.x, B1.y);
            mma16816(acc[1][2],  a1, B2.x, B2.y);
            mma16816(acc[1][3],  a1, B3.x, B3.y);
            mma16816(acc2[0][0], a0, B0.z, B0.w);
            mma16816(acc2[0][1], a0, B1.z, B1.w);
            mma16816(acc2[0][2], a0, B2.z, B2.w);
            mma16816(acc2[0][3], a0, B3.z, B3.w);
            mma16816(acc2[1][0], a1, B0.z, B0.w);
            mma16816(acc2[1][1], a1, B1.z, B1.w);
            mma16816(acc2[1][2], a1, B2.z, B2.w);
            mma16816(acc2[1][3], a1, B3.z, B3.w);
        }
    }

    asm volatile("cp.async.wait_group 0;" ::: "memory");
    __syncthreads();    // all compute done before aliasing stage buffers
    if (tid == 0) *s_nfl = 0;

    // ---- k-slice tree reduction ----
    const int slot = mh * 2 + (ks >> 1);
    float* rp = red + slot * 2048;

    if (ks & 1) {
        #pragma unroll
        for (int mg = 0; mg < 2; mg++)
            #pragma unroll
            for (int nt = 0; nt < 4; nt++)
                #pragma unroll
                for (int q = 0; q < 4; q++) {
                    rp[(mg * 32 + nt * 4 + q) * 32 + lane] = acc[mg][nt][q];
                    rp[(mg * 32 + (nt + 4) * 4 + q) * 32 + lane] = acc2[mg][nt][q];
                }
    }
    __syncthreads();
    if (!(ks & 1)) {
        #pragma unroll
        for (int mg = 0; mg < 2; mg++)
            #pragma unroll
            for (int nt = 0; nt < 4; nt++)
                #pragma unroll
                for (int q = 0; q < 4; q++) {
                    acc[mg][nt][q]  += rp[(mg * 32 + nt * 4 + q) * 32 + lane];
                    acc2[mg][nt][q] += rp[(mg * 32 + (nt + 4) * 4 + q) * 32 + lane];
                }
    }
    __syncthreads();
    if (ks == 2) {
        float* rp2 = red + (mh * 2) * 2048;
        #pragma unroll
        for (int mg = 0; mg < 2; mg++)
            #pragma unroll
            for (int nt = 0; nt < 4; nt++)
                #pragma unroll
                for (int q = 0; q < 4; q++) {
                    rp2[(mg * 32 + nt * 4 + q) * 32 + lane] = acc[mg][nt][q];
                    rp2[(mg * 32 + (nt + 4) * 4 + q) * 32 + lane] = acc2[mg][nt][q];
                }
    }
    __syncthreads();
    if (ks == 0) {
        const float* rp2 = red + (mh * 2) * 2048;
        const int gr = lane >> 2;
        const int gc = (lane & 3) * 2;
        #pragma unroll
        for (int mg = 0; mg < 2; mg++) {
            const int rr0 = mh * 32 + mg * 16 + gr;
            #pragma unroll
            for (int nt = 0; nt < 8; nt++) {
                float* a = (nt < 4) ? acc[mg][nt] : acc2[mg][nt - 4];
                float c0 = a[0] + rp2[(mg * 32 + nt * 4 + 0) * 32 + lane];
                float c1 = a[1] + rp2[(mg * 32 + nt * 4 + 1) * 32 + lane];
                float c2 = a[2] + rp2[(mg * 32 + nt * 4 + 2) * 32 + lane];
                float c3 = a[3] + rp2[(mg * 32 + nt * 4 + 3) * 32 + lane];
                const int cc = nt * 8 + gc;
                slog[rr0 * 65 + cc]           = c0;
                slog[rr0 * 65 + cc + 1]       = c1;
                slog[(rr0 + 8) * 65 + cc]     = c2;
                slog[(rr0 + 8) * 65 + cc + 1] = c3;
            }
        }
    }
    __syncthreads();

    // ---- per-token scan: top-4, logsumexp, flag near-ties ----
    if (tid < BM) {
        const float* r = slog + tid * 65;
        float m1 = -3.4e38f, m2 = -3.4e38f, m3 = -3.4e38f, m4 = -3.4e38f;
        int i1 = 0, i2 = 0, i3 = 0, i4 = 0;
        #pragma unroll
        for (int e = 0; e < NE; e++) {
            float v = r[e];
            if (v > m1)      { m4=m3;i4=i3; m3=m2;i3=i2; m2=m1;i2=i1; m1=v;i1=e; }
            else if (v > m2) { m4=m3;i4=i3; m3=m2;i3=i2; m2=v;i2=e; }
            else if (v > m3) { m4=m3;i4=i3; m3=v;i3=e; }
            else if (v > m4) { m4=v;i4=e; }
        }
        float sum = 0.f;
        #pragma unroll
        for (int e = 0; e < NE; e++) sum += expf(r[e] - m1);
        float lz = m1 + logf(sum);
        out_loss[m_base + tid] = lz * lz;

        float dd = expf(m2 - m1);
        float s1 = 1.f / (1.f + dd);
        s_s1[tid] = s1;
        s_s2[tid] = dd * s1;
        s_i1[tid] = i1;
        s_i2[tid] = i2;

        int ent = -1;
        if (m2 - m3 < TAU) {
            int fs = atomicAdd(s_nfl, 1);
            if (fs < MAXF) {
                ent = fs;
                f_tok[ent] = tid;
                f_cand[ent * 4 + 0] = i1;
                f_cand[ent * 4 + 1] = i2;
                f_cand[ent * 4 + 2] = i3;
                f_cand[ent * 4 + 3] = i4;
            }
        }
        s_fent[tid] = ent;
    }
    __syncthreads();

    // ---- exact fp32 refinement: one warp per (flagged token, candidate) ----
    {
        int nf = *s_nfl; if (nf > MAXF) nf = MAXF;
        for (int task = wid; task < nf * 4; task += 8) {
            const int fi = task >> 2, c = task & 3;
            const int tok = f_tok[fi];
            const int expert = f_cand[fi * 4 + c];
            const float* xr = x + (m_base + tok) * DIM;
            const float* wr = Wf + (size_t)expert * DIM;
            float a4[4] = {0.f, 0.f, 0.f, 0.f};
            for (int k = lane * 4; k < DIM; k += 128) {
                float4 xv = *reinterpret_cast<const float4*>(xr + k);
                float4 wv = *reinterpret_cast<const float4*>(wr + k);
                a4[0] = fmaf(xv.x, wv.x, a4[0]);
                a4[1] = fmaf(xv.y, wv.y, a4[1]);
                a4[2] = fmaf(xv.z, wv.z, a4[2]);
                a4[3] = fmaf(xv.w, wv.w, a4[3]);
            }
            float sum = (a4[0] + a4[1]) + (a4[2] + a4[3]);
            #pragma unroll
            for (int off = 16; off; off >>= 1)
                sum += __shfl_xor_sync(0xffffffffu, sum, off);
            if (lane == 0) f_val[fi * 4 + c] = sum;
        }
    }
    __syncthreads();

    // ---- flagged tokens: re-pick exact top-2 (stable ties by lower index) ----
    if (tid < BM && s_fent[tid] >= 0) {
        const int ent = s_fent[tid];
        float v1 = -3.4e38f, v2 = -3.4e38f;
        int j1 = NE, j2 = NE;
        #pragma unroll
        for (int c = 0; c < 4; c++) {
            float v = f_val[ent * 4 + c];
            int   j = f_cand[ent * 4 + c];
            bool b1 = (v > v1) || (v == v1 && j < j1);
            bool b2 = (v > v2) || (v == v2 && j < j2);
            if (b1)      { v2 = v1; j2 = j1; v1 = v; j1 = j; }
            else if (b2) { v2 = v; j2 = j; }
        }
        float dd = expf(v2 - v1);
        float s1 = 1.f / (1.f + dd);
        s_s1[tid] = s1;
        s_s2[tid] = dd * s1;
        s_i1[tid] = j1;
        s_i2[tid] = j2;
    }
    __syncthreads();

    // ---- stores ----
    float* lg = out_logits + m_base * NE;
    float* sc = out_scores + m_base * NE;
    #pragma unroll
    for (int pass = 0; pass < (BM * NE) / NTHR; pass++) {
        int idx = pass * NTHR + tid;
        int t = idx >> 6;
        int e = idx & 63;
        lg[idx] = slog[t * 65 + e];
        float sv = (e == s_i1[t]) ? s_s1[t] : ((e == s_i2[t]) ? s_s2[t] : 0.f);
        sc[idx] = sv;
    }
#undef COPY_STAGE
}

extern "C" void kernel_launch(void* const* d_in, const int* in_sizes, int n_in,
                              void* d_out, int out_size)
{
    const float* x = (const float*)d_in[0];
    const float* W = (const float*)d_in[1];
    float* out    = (float*)d_out;
    float* logits = out;
    float* scores = out + (size_t)TOKENS * NE;
    float* loss   = out + (size_t)2 * TOKENS * NE;

    prep_w<<<128, 256>>>(W);

    cudaFuncSetAttribute(topk_gate_pipe5,
                         cudaFuncAttributeMaxDynamicSharedMemorySize, SMEM_TOTAL);
    topk_gate_pipe5<<<TOKENS / BM, NTHR, SMEM_TOTAL>>>(x, W, logits, scores, loss);
}